// round 16
// baseline (speedup 1.0000x reference)
#include <cuda_runtime.h>
#include <cuda_fp16.h>
#include <cuda_bf16.h>
#include <cstdint>

// Problem constants (fixed by the reference)
#define IN_N  (512 * 512)   // input pixels per batch
#define NB    64            // batch
#define NO    (512 * 512)   // outputs
#define NK    8             // connections per output

// Scratch: input transposed to (N, B) in fp16: each index row is a contiguous
// 128B run of all 64 batch values (33.5 MB, L2-resident).
__device__ __align__(256) __half g_xTh[(size_t)IN_N * NB];

static __device__ __forceinline__ unsigned int h2bits(__half2 h) {
    return *reinterpret_cast<unsigned int*>(&h);
}

// ---------------------------------------------------------------------------
// Kernel 1: transpose (B, N) f32 -> (N, B) f16 — wide-tile version.
// Tile: 512 n x 64 b per block (512 blocks). Each block reads 2 KB
// CONTIGUOUS per batch row (vs 512B before) -> 4x better DRAM row-buffer
// locality, which is the remaining untested binder for the stubborn 17us.
//
// smem: s[512][32] uints (64 KB). (n=4q+e, bh) stored at word
//   n*32 + 4*((bh>>2) ^ (q&7)) + (bh&3)
// STS: 2-way conflict (same as R12). Phase 2: per 8-lane phase the 8
// swizzled 16B chunks cover all 32 banks -> conflict-free LDS.128; batch
// groups come out in order (low 2 bits unscrambled), STG 512B/warp.
// Output bit-identical to R12's g_xTh.
// ---------------------------------------------------------------------------
__global__ void __launch_bounds__(256) transpose_kernel(const float* __restrict__ in) {
    __shared__ __align__(16) unsigned int s[512 * 32];   // 64 KB
    const int n0 = blockIdx.x * 512;
    const int t  = threadIdx.x;

    const int q0 = t & 15;        // base n-quad (0..15)
    const int b0 = t >> 4;        // batch-pair (0..15)

    // ---- Phase 1: long-run loads + convert + swizzled STS ----
#pragma unroll
    for (int i = 0; i < 2; i++) {
        const int bh    = b0 + 16 * i;            // 0..31
        const int chunk = bh >> 2;
        const int r2    = bh & 3;
        const float4* __restrict__ r0p =
            reinterpret_cast<const float4*>(in + (size_t)(2 * bh) * IN_N);
        const float4* __restrict__ r1p =
            reinterpret_cast<const float4*>(in + (size_t)(2 * bh + 1) * IN_N);
#pragma unroll
        for (int jg = 0; jg < 2; jg++) {
            // Front-batch 8 independent LDG.128 (4 n-groups x 2 rows).
            float4 A[4], B[4];
#pragma unroll
            for (int j4 = 0; j4 < 4; j4++) {
                const int q = q0 + 16 * (jg * 4 + j4);   // 0..127
                A[j4] = __ldcs(&r0p[(n0 >> 2) + q]);
                B[j4] = __ldcs(&r1p[(n0 >> 2) + q]);
            }
#pragma unroll
            for (int j4 = 0; j4 < 4; j4++) {
                const int q  = q0 + 16 * (jg * 4 + j4);
                const int sw = chunk ^ (q & 7);          // q&7 == q0&7
                float av[4] = {A[j4].x, A[j4].y, A[j4].z, A[j4].w};
                float bv[4] = {B[j4].x, B[j4].y, B[j4].z, B[j4].w};
#pragma unroll
                for (int e = 0; e < 4; e++) {
                    const int row = 4 * q + e;           // 0..511
                    s[row * 32 + sw * 4 + r2] =
                        h2bits(__floats2half2_rn(av[e], bv[e]));
                }
            }
        }
    }
    __syncthreads();

    // ---- Phase 2: conflict-free LDS.128 + contiguous STG.128 ----
    uint4* __restrict__ xT4 = reinterpret_cast<uint4*>(g_xTh);
#pragma unroll
    for (int i1 = 0; i1 < 16; i1++) {
        const int u  = t + 256 * i1;                     // 0..4095
        const int nl = u >> 3;                           // 0..511
        const int g  = u & 7;                            // 16B chunk of row
        const int sw = g ^ ((nl >> 2) & 7);
        uint4 v = *reinterpret_cast<const uint4*>(&s[nl * 32 + sw * 4]);
        xT4[(size_t)(n0 + nl) * 8 + g] = v;              // 512B/warp contiguous
    }
}

// ---------------------------------------------------------------------------
// Kernel 2: gather + weighted reduce with packed HFMA2 accumulation.
// (EXACT R7/R12 kernel — ~94% of the LTS byte cap, compulsory-only DRAM.)
// ---------------------------------------------------------------------------
__global__ void __launch_bounds__(256) sparse_linear_kernel(
    const int*   __restrict__ conn,
    const float* __restrict__ w,
    float*       __restrict__ out)
{
    __shared__ float so[64][33];     // [batch][o_local], pitch 33

    const int warp   = threadIdx.x >> 5;
    const int lane   = threadIdx.x & 31;
    const int o_base = blockIdx.x * 32;
    const int o_warp = o_base + warp * 4;
    const int j      = lane >> 3;    // output within warp's 4
    const int c      = lane & 7;     // batch chunk (8 batches)

    // Coalesced: warp's 4 conn/weight rows (4 x 8 = 32 elems)
    const int   ci  = conn[(size_t)o_warp * NK + lane];
    const float wf  = w   [(size_t)o_warp * NK + lane];
    const int   wib = (int)__half_as_ushort(__float2half_rn(wf));

    const uint4* __restrict__ xT4 = reinterpret_cast<const uint4*>(g_xTh);

    __half2 accE[4], accO[4];        // even-k / odd-k chains (depth 4 each)
#pragma unroll
    for (int m = 0; m < 4; m++) {
        accE[m] = __half2half2(__ushort_as_half((unsigned short)0));
        accO[m] = accE[m];
    }

#pragma unroll
    for (int k = 0; k < NK; k++) {
        int src   = (lane & 24) + k;                    // lane j*8 + k
        int   idx = __shfl_sync(0xffffffffu, ci,  src);
        int   wb  = __shfl_sync(0xffffffffu, wib, src);
        __half2 wk2 = __half2half2(__ushort_as_half((unsigned short)wb));
        uint4 v = xT4[(size_t)idx * 8 + c];             // 512B/warp: 4 rows
        __half2* acc = (k & 1) ? accO : accE;
        acc[0] = __hfma2(wk2, *reinterpret_cast<__half2*>(&v.x), acc[0]);
        acc[1] = __hfma2(wk2, *reinterpret_cast<__half2*>(&v.y), acc[1]);
        acc[2] = __hfma2(wk2, *reinterpret_cast<__half2*>(&v.z), acc[2]);
        acc[3] = __hfma2(wk2, *reinterpret_cast<__half2*>(&v.w), acc[3]);
    }

    // Epilogue: merge chains in fp32, stage to smem.
#pragma unroll
    for (int m = 0; m < 4; m++) {
        float2 e = __half22float2(accE[m]);
        float2 o = __half22float2(accO[m]);
        so[c * 8 + 2 * m    ][warp * 4 + j] = e.x + o.x;
        so[c * 8 + 2 * m + 1][warp * 4 + j] = e.y + o.y;
    }
    __syncthreads();

    // Coalesced write-out: lane oc -> output column, 8 batch rows per thread
    const int oc = threadIdx.x & 31;
    const int br = threadIdx.x >> 5;
#pragma unroll
    for (int i = 0; i < 8; i++) {
        int b = br * 8 + i;
        out[(size_t)b * NO + o_base + oc] = so[b][oc];  // conflict-free LDS
    }
}

extern "C" void kernel_launch(void* const* d_in, const int* in_sizes, int n_in,
                              void* d_out, int out_size) {
    const float* input = (const float*)d_in[0];   // (64, 512, 512) f32
    const int*   conn  = (const int*)  d_in[1];   // (O, 8) i32
    const float* wts   = (const float*)d_in[2];   // (O, 8) f32
    float*       out   = (float*)d_out;           // (64, O) f32

    transpose_kernel<<<IN_N / 512, 256>>>(input);
    sparse_linear_kernel<<<NO / 32, 256>>>(conn, wts, out);
}

// round 17
// speedup vs baseline: 1.0839x; 1.0839x over previous
#include <cuda_runtime.h>
#include <cuda_fp16.h>
#include <cuda_bf16.h>
#include <cstdint>

// Problem constants (fixed by the reference)
#define IN_N  (512 * 512)   // input pixels per batch
#define NB    64            // batch
#define NO    (512 * 512)   // outputs
#define NK    8             // connections per output

// Scratch: input transposed to (N, B) in fp16: each index row is a contiguous
// 128B run of all 64 batch values (33.5 MB, L2-resident).
__device__ __align__(256) __half g_xTh[(size_t)IN_N * NB];

static __device__ __forceinline__ unsigned int h2bits(__half2 h) {
    return *reinterpret_cast<unsigned int*>(&h);
}

// ---------------------------------------------------------------------------
// Kernel 1: transpose (B, N) f32 -> (N, B) f16 (128n x 64b tiles, streaming
// input loads). Proven R12/R14 data path — xTh output bit-identical.
// ---------------------------------------------------------------------------
__global__ void __launch_bounds__(256) transpose_kernel(const float* __restrict__ in) {
    __shared__ __align__(16) unsigned int s[128 * 32];   // 16 KB
    const int n0 = blockIdx.x * 128;
    const int t  = threadIdx.x;

    const int q0 = t & 15;        // base n-quad
    const int b0 = t >> 4;        // base batch-pair (0..15)

    float4 A[2][2], B[2][2];      // [i: bh half][j: q half]
#pragma unroll
    for (int i = 0; i < 2; i++) {
        const int bh = b0 + 16 * i;               // 0..31
        const float4* __restrict__ r0 =
            reinterpret_cast<const float4*>(in + (size_t)(2 * bh) * IN_N);
        const float4* __restrict__ r1 =
            reinterpret_cast<const float4*>(in + (size_t)(2 * bh + 1) * IN_N);
#pragma unroll
        for (int jq = 0; jq < 2; jq++) {
            const int q = q0 + 16 * jq;           // 0..31
            A[i][jq] = __ldcs(&r0[(n0 >> 2) + q]);   // evict-first streaming
            B[i][jq] = __ldcs(&r1[(n0 >> 2) + q]);
        }
    }

#pragma unroll
    for (int i = 0; i < 2; i++) {
        const int bh    = b0 + 16 * i;
        const int chunk = bh >> 2;                // 0..7
        const int r2    = bh & 3;
#pragma unroll
        for (int jq = 0; jq < 2; jq++) {
            const int q = q0 + 16 * jq;           // row>>2 == q
            float av[4] = {A[i][jq].x, A[i][jq].y, A[i][jq].z, A[i][jq].w};
            float bv[4] = {B[i][jq].x, B[i][jq].y, B[i][jq].z, B[i][jq].w};
            const int sw = chunk ^ (q & 7);
#pragma unroll
            for (int e = 0; e < 4; e++) {
                int row = 4 * q + e;              // 0..127
                s[row * 32 + sw * 4 + r2] =
                    h2bits(__floats2half2_rn(av[e], bv[e]));
            }
        }
    }
    __syncthreads();

    // ---- Phase 2: LDS.128 + contiguous STG.128 (xTh: normal policy, keep
    //      resident in L2 for the gather) ----
    uint4* __restrict__ xT4 = reinterpret_cast<uint4*>(g_xTh);
#pragma unroll
    for (int i1 = 0; i1 < 4; i1++) {
        int u  = t + 256 * i1;                    // 0..1023
        int nl = u >> 3;                          // 0..127
        int g  = u & 7;                           // 16B chunk of 128B row
        int sw = g ^ ((nl >> 2) & 7);
        uint4 v = *reinterpret_cast<const uint4*>(&s[nl * 32 + sw * 4]);
        xT4[(size_t)(n0 + nl) * 8 + g] = v;       // 512B/warp contiguous
    }
}

// ---------------------------------------------------------------------------
// Kernel 2: gather + weighted reduce with packed HFMA2 accumulation.
// Changes vs R7/R12: conn/w loads use __ldcs (single-use, don't pollute L2);
// out stores use __stcs (evict-first -> writebacks drain DURING this kernel,
// which has DRAM headroom, instead of stalling the next replay's transpose).
// Math bit-identical.
// ---------------------------------------------------------------------------
__global__ void __launch_bounds__(256) sparse_linear_kernel(
    const int*   __restrict__ conn,
    const float* __restrict__ w,
    float*       __restrict__ out)
{
    __shared__ float so[64][33];     // [batch][o_local], pitch 33

    const int warp   = threadIdx.x >> 5;
    const int lane   = threadIdx.x & 31;
    const int o_base = blockIdx.x * 32;
    const int o_warp = o_base + warp * 4;
    const int j      = lane >> 3;    // output within warp's 4
    const int c      = lane & 7;     // batch chunk (8 batches)

    // Coalesced, streaming: warp's 4 conn/weight rows (4 x 8 = 32 elems)
    const int   ci  = __ldcs(&conn[(size_t)o_warp * NK + lane]);
    const float wf  = __ldcs(&w   [(size_t)o_warp * NK + lane]);
    const int   wib = (int)__half_as_ushort(__float2half_rn(wf));

    const uint4* __restrict__ xT4 = reinterpret_cast<const uint4*>(g_xTh);

    __half2 accE[4], accO[4];        // even-k / odd-k chains (depth 4 each)
#pragma unroll
    for (int m = 0; m < 4; m++) {
        accE[m] = __half2half2(__ushort_as_half((unsigned short)0));
        accO[m] = accE[m];
    }

#pragma unroll
    for (int k = 0; k < NK; k++) {
        int src   = (lane & 24) + k;                    // lane j*8 + k
        int   idx = __shfl_sync(0xffffffffu, ci,  src);
        int   wb  = __shfl_sync(0xffffffffu, wib, src);
        __half2 wk2 = __half2half2(__ushort_as_half((unsigned short)wb));
        uint4 v = xT4[(size_t)idx * 8 + c];             // 512B/warp: 4 rows
        __half2* acc = (k & 1) ? accO : accE;
        acc[0] = __hfma2(wk2, *reinterpret_cast<__half2*>(&v.x), acc[0]);
        acc[1] = __hfma2(wk2, *reinterpret_cast<__half2*>(&v.y), acc[1]);
        acc[2] = __hfma2(wk2, *reinterpret_cast<__half2*>(&v.z), acc[2]);
        acc[3] = __hfma2(wk2, *reinterpret_cast<__half2*>(&v.w), acc[3]);
    }

    // Epilogue: merge chains in fp32, stage to smem.
#pragma unroll
    for (int m = 0; m < 4; m++) {
        float2 e = __half22float2(accE[m]);
        float2 o = __half22float2(accO[m]);
        so[c * 8 + 2 * m    ][warp * 4 + j] = e.x + o.x;
        so[c * 8 + 2 * m + 1][warp * 4 + j] = e.y + o.y;
    }
    __syncthreads();

    // Coalesced write-out (streaming stores: drain writebacks now, keep L2
    // clean for the next replay's transpose).
    const int oc = threadIdx.x & 31;
    const int br = threadIdx.x >> 5;
#pragma unroll
    for (int i = 0; i < 8; i++) {
        int b = br * 8 + i;
        __stcs(&out[(size_t)b * NO + o_base + oc], so[b][oc]);
    }
}

extern "C" void kernel_launch(void* const* d_in, const int* in_sizes, int n_in,
                              void* d_out, int out_size) {
    const float* input = (const float*)d_in[0];   // (64, 512, 512) f32
    const int*   conn  = (const int*)  d_in[1];   // (O, 8) i32
    const float* wts   = (const float*)d_in[2];   // (O, 8) f32
    float*       out   = (float*)d_out;           // (64, O) f32

    transpose_kernel<<<IN_N / 128, 256>>>(input);
    sparse_linear_kernel<<<NO / 32, 256>>>(conn, wts, out);
}